// round 15
// baseline (speedup 1.0000x reference)
#include <cuda_runtime.h>
#include <cstdint>
#include <cstddef>

// ============================================================================
// RhythmMemoryUpdater — GB300 sm_103a (base sm_103 target)
//   L = 1  =>  out = node_memories; out[node_ids] = LN( x @ W'^T + lin_b )
//   x = [messages | node_memories[node_ids]] (K=256)
//   W'[d,c] = lin_w[d,c] * conv_w[c, period/2]
//
// R15: R14 skeleton (kh1 staging/convert specialists, cp.async, named
// barriers, kh0 epilogue) with bf16 MMA (m16n8k16) + static W-split
// (W' = Wh + Wl, both bf16 in regs; x bf16 once) for precision (R11-proven
// 8.4e-4). Halves the dominant crossbar term (x B-fragment bytes).
// ============================================================================

#define NDIM 128
#define KDIM 256
#define TILE_M 64
#define NTHREADS 512
#define NCTAS 148
#define RAW_STRIDE 264           // u32 per raw f32 staged row
#define XB_STRIDE 136            // u32 (bf16x2) per packed row; bank 4r+kp
#define SD_STRIDE 132            // floats per D row (conflict-free)

__device__ uint8_t g_mask[1 << 20];

// ---------------- helpers ----------------
__device__ __forceinline__ uint32_t smem_u32(const void* p) {
    uint32_t a;
    asm("{ .reg .u64 t; cvta.to.shared.u64 t, %1; cvt.u32.u64 %0, t; }" : "=r"(a) : "l"(p));
    return a;
}
__device__ __forceinline__ uint32_t pack_bf16(float lo, float hi) {
    uint32_t r;
    asm("cvt.rn.bf16x2.f32 %0, %1, %2;" : "=r"(r) : "f"(hi), "f"(lo));
    return r;
}
__device__ __forceinline__ void mma_bf16(float c[4], uint32_t a0, uint32_t a1,
                                         uint32_t a2, uint32_t a3,
                                         uint32_t b0, uint32_t b1) {
    asm volatile(
        "mma.sync.aligned.m16n8k16.row.col.f32.bf16.bf16.f32 "
        "{%0,%1,%2,%3}, {%4,%5,%6,%7}, {%8,%9}, {%0,%1,%2,%3};"
        : "+f"(c[0]), "+f"(c[1]), "+f"(c[2]), "+f"(c[3])
        : "r"(a0), "r"(a1), "r"(a2), "r"(a3), "r"(b0), "r"(b1));
}
__device__ __forceinline__ void cp_async16(uint32_t dst, const void* src) {
    asm volatile("cp.async.cg.shared.global [%0], [%1], 16;" :: "r"(dst), "l"(src));
}
#define CP_COMMIT() asm volatile("cp.async.commit_group;" ::: "memory")
#define CP_WAIT0()  asm volatile("cp.async.wait_group 0;" ::: "memory")

// named barrier among the 256 kh0 threads (tid 0..255)
#define KH0_BAR() asm volatile("bar.sync 1, 256;" ::: "memory")
// named barrier among the 256 kh1 threads (tid 256..511)
#define KH1_BAR() asm volatile("bar.sync 2, 256;" ::: "memory")

// ============================================================================
// mask + copy kernels
// ============================================================================
__global__ void __launch_bounds__(256) k_clear(int nbytes16) {
    uint4 z = make_uint4(0, 0, 0, 0);
    uint4* m = (uint4*)g_mask;
    for (int i = blockIdx.x * 256 + threadIdx.x; i < nbytes16; i += gridDim.x * 256)
        m[i] = z;
}
__global__ void __launch_bounds__(256) k_mark(const int* __restrict__ ids, int n) {
    int i = blockIdx.x * 256 + threadIdx.x;
    if (i < n) g_mask[ids[i]] = 1;
}
__global__ void __launch_bounds__(256) k_copy_masked(const float4* __restrict__ src,
                                                     float4* __restrict__ dst,
                                                     int nf4) {
    int stride = gridDim.x * 256;
    for (int i = blockIdx.x * 256 + threadIdx.x; i < nf4; i += stride) {
        int row = i >> 5;
        if (g_mask[row] == 0) dst[i] = src[i];
    }
}

// ============================================================================
// persistent GEMM + LayerNorm + scatter
// ============================================================================
__global__ void __launch_bounds__(NTHREADS, 1) rhythm_gemm(
    const int*   __restrict__ node_ids,
    const float* __restrict__ messages,
    const float* __restrict__ node_mem,
    const float* __restrict__ conv_w,
    const float* __restrict__ lin_w,
    const float* __restrict__ lin_b,
    const float* __restrict__ ln_g,
    const float* __restrict__ ln_bt,
    float*       __restrict__ out,
    int ntiles, int period, int pad)
{
    // ---- dynamic smem carve ----
    extern __shared__ uint32_t dyn[];
    uint32_t* sXraw  = dyn;                                     // 64*264 u32
    uint32_t* sXb    = sXraw + TILE_M * RAW_STRIDE;             // 2*64*136 u32
    float4*   s_comb = (float4*)(sXb + 2 * TILE_M * XB_STRIDE); // 2048 f4
    float*    sD     = (float*)(s_comb + 2048);                 // 64*132 f
    int*      s_node = (int*)(sD + TILE_M * SD_STRIDE);         // 2*64
    float*    s_gam  = (float*)(s_node + 2 * TILE_M);           // 128
    float*    s_bet  = s_gam + NDIM;                            // 128

    const int tid  = threadIdx.x;
    const int lane = tid & 31;
    const int wid  = tid >> 5;        // 0..15
    const int kh   = wid >> 3;        // K-half
    const int dblk = wid & 7;         // d block

    // ---- static per-warp W' split fragments (Wh + Wl, bf16x2) ----
    const int d1 = dblk * 16 + (lane >> 2);
    const int d2 = d1 + 8;

    uint32_t aregH[8][4], aregL[8][4];
#pragma unroll
    for (int kt = 0; kt < 8; kt++) {
        int k1 = kh * 128 + kt * 16 + (lane & 3) * 2;
#pragma unroll
        for (int h = 0; h < 2; h++) {          // h=0 -> k1, h=1 -> k1+8
            int kk = k1 + 8 * h;
            float wa = __ldg(conv_w + kk * period + pad);
            float wb = __ldg(conv_w + (kk + 1) * period + pad);
            float w10 = __ldg(lin_w + d1 * KDIM + kk) * wa;
            float w11 = __ldg(lin_w + d1 * KDIM + kk + 1) * wb;
            float w20 = __ldg(lin_w + d2 * KDIM + kk) * wa;
            float w21 = __ldg(lin_w + d2 * KDIM + kk + 1) * wb;
            uint32_t h1 = pack_bf16(w10, w11);
            uint32_t h2 = pack_bf16(w20, w21);
            aregH[kt][2 * h]     = h1;
            aregH[kt][2 * h + 1] = h2;
            float r10 = w10 - __uint_as_float(h1 << 16);
            float r11 = w11 - __uint_as_float(h1 & 0xffff0000u);
            float r20 = w20 - __uint_as_float(h2 << 16);
            float r21 = w21 - __uint_as_float(h2 & 0xffff0000u);
            aregL[kt][2 * h]     = pack_bf16(r10, r11);
            aregL[kt][2 * h + 1] = pack_bf16(r20, r21);
        }
    }
    const float bia1 = __ldg(lin_b + d1), bia2 = __ldg(lin_b + d2);
    if (tid < NDIM) {
        s_gam[tid] = ln_g[tid];
        s_bet[tid] = ln_bt[tid];
    }

    // ---- kh1-only: cp.async stage raw f32 x into sXraw ----
    auto stage_tile = [&](int tile, int it_idx) {
        if (tile >= ntiles) return;
        const int nslot = it_idx & 1;
        const int t = tid - 256;          // 0..255
#pragma unroll
        for (int i = 0; i < 16; i++) {
            int idx = i * 256 + t;        // 4096 chunks of 16B
            int row = idx >> 6, c = idx & 63;
            long long gr = (long long)tile * TILE_M + row;
            const float4* src;
            if (c < 32) {
                src = (const float4*)messages + gr * 32 + c;
            } else {
                int nd = __ldg(node_ids + gr);
                if (c == 32) s_node[nslot * TILE_M + row] = nd;
                src = (const float4*)node_mem + (long long)nd * 32 + (c - 32);
            }
            cp_async16(smem_u32(sXraw + row * RAW_STRIDE + c * 4), src);
        }
    };

    // ---- kh1-only: convert sXraw -> packed bf16x2 (k-pair permuted) ----
    //      slot row = 128 u32; fragment pair (kp, kp+8 elems) adjacent:
    //      q[2kp] = pack(k16+2kp, +1), q[2kp+1] = pack(k16+8+2kp, +1)
    auto convert_slot = [&](int it_idx) {
        uint32_t* slotS = sXb + (size_t)(it_idx & 1) * TILE_M * XB_STRIDE;
        const int t = tid - 256;          // 0..255
#pragma unroll
        for (int i = 0; i < 4; i++) {
            int g = i * 256 + t;          // 1024 groups of 16 floats
            int row = g >> 4, kt = g & 15;
            const float4* p = (const float4*)(sXraw + row * RAW_STRIDE + kt * 16);
            float4 f0 = p[0], f1 = p[1], f2 = p[2], f3 = p[3];
            uint32_t* q = slotS + row * XB_STRIDE + kt * 8;
            ((uint4*)q)[0] = make_uint4(pack_bf16(f0.x, f0.y), pack_bf16(f2.x, f2.y),
                                        pack_bf16(f0.z, f0.w), pack_bf16(f2.z, f2.w));
            ((uint4*)q)[1] = make_uint4(pack_bf16(f1.x, f1.y), pack_bf16(f3.x, f3.y),
                                        pack_bf16(f1.z, f1.w), pack_bf16(f3.z, f3.w));
        }
    };

    // ---- prologue: kh1 stages + converts tile 0 ----
    if (kh == 1) {
        stage_tile(blockIdx.x, 0);
        CP_COMMIT();
        CP_WAIT0();
        KH1_BAR();                        // all kh1 threads' chunks visible
        if (blockIdx.x < ntiles) convert_slot(0);
    }

    for (int it = 0;; it++) {
        int tile = blockIdx.x + it * gridDim.x;
        if (tile >= ntiles) break;
        const int slot = it & 1;

        __syncthreads();          // packed slot + s_node visible
                                  // prev iter's sD/s_comb fully consumed

        // ======== MMA: per warp 16 d x 64 batch, K-half, Wh+Wl ========
        const uint32_t* xb = sXb + (size_t)slot * TILE_M * XB_STRIDE
                           + (lane >> 2) * XB_STRIDE + kh * 64 + (lane & 3) * 2;
        float cacc[8][4];
#pragma unroll
        for (int nt = 0; nt < 8; nt++)
#pragma unroll
            for (int j = 0; j < 4; j++) cacc[nt][j] = 0.f;

#pragma unroll
        for (int kt = 0; kt < 8; kt++) {
            uint2 bp[8];
#pragma unroll
            for (int nt = 0; nt < 8; nt++)
                bp[nt] = *(const uint2*)(xb + nt * 8 * XB_STRIDE + kt * 8);
#pragma unroll
            for (int nt = 0; nt < 8; nt++) {
                mma_bf16(cacc[nt], aregH[kt][0], aregH[kt][1],
                         aregH[kt][2], aregH[kt][3], bp[nt].x, bp[nt].y);
                mma_bf16(cacc[nt], aregL[kt][0], aregL[kt][1],
                         aregL[kt][2], aregL[kt][3], bp[nt].x, bp[nt].y);
            }
        }

        // ---- K-high warps publish partials ----
        if (kh == 1) {
#pragma unroll
            for (int nt = 0; nt < 8; nt++)
                s_comb[(dblk * 8 + nt) * 32 + lane] =
                    make_float4(cacc[nt][0], cacc[nt][1], cacc[nt][2], cacc[nt][3]);
        }
        __syncthreads();          // slot reads done + s_comb visible

        if (kh == 1) {
            // ===== kh1: stage raw it+1, wait, convert into slot^1 =====
            stage_tile(tile + gridDim.x, it + 1);
            CP_COMMIT();
            CP_WAIT0();           // this thread's chunks landed
            KH1_BAR();            // ALL kh1 threads' chunks visible
            if (tile + gridDim.x < ntiles) convert_slot(it + 1);
        } else {
            // ============ kh0: combine + bias -> sD =======================
#pragma unroll
            for (int nt = 0; nt < 8; nt++) {
                float4 p = s_comb[(dblk * 8 + nt) * 32 + lane];
                int brA = nt * 8 + (lane & 3) * 2;
                sD[brA * SD_STRIDE + d1]       = cacc[nt][0] + p.x + bia1;
                sD[(brA + 1) * SD_STRIDE + d1] = cacc[nt][1] + p.y + bia1;
                sD[brA * SD_STRIDE + d2]       = cacc[nt][2] + p.z + bia2;
                sD[(brA + 1) * SD_STRIDE + d2] = cacc[nt][3] + p.w + bia2;
            }
            KH0_BAR();            // sD complete (kh0-only barrier)

            // ============ kh0: LayerNorm + coalesced scatter (2 passes) ====
#pragma unroll
            for (int p = 0; p < 2; p++) {
                const int r  = p * 32 + (tid >> 3);   // row 0..63
                const int cc = tid & 7;               // f4-chunks cc,cc+8,cc+16,cc+24
                float4 v[4];
                float vsum = 0.f, vsq = 0.f;
#pragma unroll
                for (int j = 0; j < 4; j++) {
                    v[j] = *(const float4*)&sD[r * SD_STRIDE + (cc + 8 * j) * 4];
                    vsum += v[j].x + v[j].y + v[j].z + v[j].w;
                    vsq  += v[j].x * v[j].x + v[j].y * v[j].y
                          + v[j].z * v[j].z + v[j].w * v[j].w;
                }
                vsum += __shfl_xor_sync(0xffffffffu, vsum, 1);
                vsq  += __shfl_xor_sync(0xffffffffu, vsq, 1);
                vsum += __shfl_xor_sync(0xffffffffu, vsum, 2);
                vsq  += __shfl_xor_sync(0xffffffffu, vsq, 2);
                vsum += __shfl_xor_sync(0xffffffffu, vsum, 4);
                vsq  += __shfl_xor_sync(0xffffffffu, vsq, 4);
                float mean = vsum * (1.0f / 128.0f);
                float var  = vsq * (1.0f / 128.0f) - mean * mean;
                float rstd = rsqrtf(var + 1e-5f);

                long long nd = s_node[slot * TILE_M + r];
                float* orow = out + nd * NDIM;
#pragma unroll
                for (int j = 0; j < 4; j++) {
                    int cb = (cc + 8 * j) * 4;
                    const float4 g  = *(const float4*)&s_gam[cb];
                    const float4 bt = *(const float4*)&s_bet[cb];
                    float4 o;
                    o.x = (v[j].x - mean) * rstd * g.x + bt.x;
                    o.y = (v[j].y - mean) * rstd * g.y + bt.y;
                    o.z = (v[j].z - mean) * rstd * g.z + bt.z;
                    o.w = (v[j].w - mean) * rstd * g.w + bt.w;
                    *(float4*)&orow[cb] = o;
                }
            }
        }
        // loop-top __syncthreads rejoins kh0/kh1
    }
}

// ============================================================================
// launch
// ============================================================================
extern "C" void kernel_launch(void* const* d_in, const int* in_sizes, int n_in,
                              void* d_out, int out_size) {
    const int*   node_ids = (const int*)  d_in[0];
    const float* messages = (const float*)d_in[1];
    const float* node_mem = (const float*)d_in[2];
    const float* conv_w   = (const float*)d_in[3];
    const float* lin_w    = (const float*)d_in[4];
    const float* lin_b    = (const float*)d_in[5];
    const float* ln_g     = (const float*)d_in[6];
    const float* ln_bt    = (const float*)d_in[7];
    float* out = (float*)d_out;

    int Btot    = in_sizes[1] / NDIM;            // 262144
    int ntiles  = Btot / TILE_M;                 // 4096
    int period  = in_sizes[3] / KDIM;            // 7
    int pad     = period / 2;                    // 3 (L == 1 path)
    int nf4     = out_size / 4;

    // mask of rows updated by the scatter
    k_clear<<<64, 256>>>((1 << 20) / 16);
    k_mark<<<(Btot + 255) / 256, 256>>>(node_ids, Btot);

    // copy non-updated rows at full occupancy
    k_copy_masked<<<2048, 256>>>((const float4*)node_mem, (float4*)out, nf4);

    // persistent GEMM + LN + scatter
    const int dyn_smem = (TILE_M * RAW_STRIDE + 2 * TILE_M * XB_STRIDE) * 4
                       + 2048 * 16                        // s_comb
                       + TILE_M * SD_STRIDE * 4           // sD
                       + 2 * TILE_M * 4 + 2 * NDIM * 4;   // node ring + ln vecs
    static int configured = -1;
    if (configured != dyn_smem) {
        cudaFuncSetAttribute(rhythm_gemm, cudaFuncAttributeMaxDynamicSharedMemorySize,
                             dyn_smem);
        configured = dyn_smem;
    }
    rhythm_gemm<<<NCTAS, NTHREADS, dyn_smem>>>(node_ids, messages, node_mem, conv_w,
                                               lin_w, lin_b, ln_g, ln_bt, out,
                                               ntiles, period, pad);
}

// round 16
// speedup vs baseline: 1.0767x; 1.0767x over previous
#include <cuda_runtime.h>
#include <cstdint>
#include <cstddef>

// ============================================================================
// RhythmMemoryUpdater — GB300 sm_103a (base sm_103 target: mma.sync tf32 path)
//   L = 1  =>  out = node_memories; out[node_ids] = LN( x @ W'^T + lin_b )
//   x = [messages | node_memories[node_ids]] (K=256)
//   W'[d,c] = lin_w[d,c] * conv_w[c, period/2]
//
// R16: R14 gemm (best: 251.6us) + R14 copy kernel, but the copy runs on a
// SIDE STREAM concurrently with the gemm (event fork/join, graph-capturable).
// Copy rows and scattered rows are disjoint (mask) -> safe concurrency.
// ============================================================================

#define NDIM 128
#define KDIM 256
#define TILE_M 64
#define NTHREADS 512
#define NCTAS 148
#define NSLOTS 4                 // node-id ring depth
#define SX_STRIDE 264            // u32 per staged row: conflict-free LDS.64
#define SD_STRIDE 132            // floats per D row (conflict-free)

__device__ uint8_t g_mask[1 << 20];

// ---------------- helpers ----------------
__device__ __forceinline__ uint32_t smem_u32(const void* p) {
    uint32_t a;
    asm("{ .reg .u64 t; cvta.to.shared.u64 t, %1; cvt.u32.u64 %0, t; }" : "=r"(a) : "l"(p));
    return a;
}
__device__ __forceinline__ uint32_t f2tf32(float f) {
    uint32_t o;
    asm("cvt.rna.tf32.f32 %0, %1;" : "=r"(o) : "f"(f));
    return o;
}
__device__ __forceinline__ void mma_tf32(float c[4], uint32_t a0, uint32_t a1,
                                         uint32_t a2, uint32_t a3,
                                         uint32_t b0, uint32_t b1) {
    asm volatile(
        "mma.sync.aligned.m16n8k8.row.col.f32.tf32.tf32.f32 "
        "{%0,%1,%2,%3}, {%4,%5,%6,%7}, {%8,%9}, {%0,%1,%2,%3};"
        : "+f"(c[0]), "+f"(c[1]), "+f"(c[2]), "+f"(c[3])
        : "r"(a0), "r"(a1), "r"(a2), "r"(a3), "r"(b0), "r"(b1));
}
__device__ __forceinline__ void cp_async16(uint32_t dst, const void* src) {
    asm volatile("cp.async.cg.shared.global [%0], [%1], 16;" :: "r"(dst), "l"(src));
}
#define CP_COMMIT() asm volatile("cp.async.commit_group;" ::: "memory")
#define CP_WAIT1()  asm volatile("cp.async.wait_group 1;" ::: "memory")

// named barrier among the 256 kh0 threads (tid 0..255)
#define KH0_BAR() asm volatile("bar.sync 1, 256;" ::: "memory")
// named barrier among the 256 kh1 threads (tid 256..511)
#define KH1_BAR() asm volatile("bar.sync 2, 256;" ::: "memory")

// ============================================================================
// mask + copy kernels
// ============================================================================
__global__ void __launch_bounds__(256) k_clear(int nbytes16) {
    uint4 z = make_uint4(0, 0, 0, 0);
    uint4* m = (uint4*)g_mask;
    for (int i = blockIdx.x * 256 + threadIdx.x; i < nbytes16; i += gridDim.x * 256)
        m[i] = z;
}
__global__ void __launch_bounds__(256) k_mark(const int* __restrict__ ids, int n) {
    int i = blockIdx.x * 256 + threadIdx.x;
    if (i < n) g_mask[ids[i]] = 1;
}
__global__ void __launch_bounds__(256) k_copy_masked(const float4* __restrict__ src,
                                                     float4* __restrict__ dst,
                                                     int nf4) {
    int stride = gridDim.x * 256;
    for (int i = blockIdx.x * 256 + threadIdx.x; i < nf4; i += stride) {
        int row = i >> 5;
        if (g_mask[row] == 0) dst[i] = src[i];
    }
}

// ============================================================================
// persistent GEMM + LayerNorm + scatter (R14 — unchanged)
// ============================================================================
__global__ void __launch_bounds__(NTHREADS, 1) rhythm_gemm(
    const int*   __restrict__ node_ids,
    const float* __restrict__ messages,
    const float* __restrict__ node_mem,
    const float* __restrict__ conv_w,
    const float* __restrict__ lin_w,
    const float* __restrict__ lin_b,
    const float* __restrict__ ln_g,
    const float* __restrict__ ln_bt,
    float*       __restrict__ out,
    int ntiles, int period, int pad)
{
    // ---- dynamic smem carve ----
    extern __shared__ uint32_t dyn[];
    uint32_t* sX     = dyn;                                     // 2*64*264 u32
    float4*   s_comb = (float4*)(dyn + 2 * TILE_M * SX_STRIDE); // 2048 f4
    float*    sD     = (float*)(s_comb + 2048);                 // 64*132 f
    int*      s_node = (int*)(sD + TILE_M * SD_STRIDE);         // 4*64
    float*    s_gam  = (float*)(s_node + NSLOTS * TILE_M);      // 128
    float*    s_bet  = s_gam + NDIM;                            // 128

    const int tid  = threadIdx.x;
    const int lane = tid & 31;
    const int wid  = tid >> 5;        // 0..15
    const int kh   = wid >> 3;        // K-half
    const int dblk = wid & 7;         // d block

    // ---- static per-warp W' fragments (A operand of C^T = W' * x^T) ----
    const int d1 = dblk * 16 + (lane >> 2);
    const int d2 = d1 + 8;
    const int kbase = lane & 3;

    uint32_t areg[16][4];
#pragma unroll
    for (int kt = 0; kt < 16; kt++) {
        int k1 = kh * 128 + kt * 8 + kbase, k2 = k1 + 4;
        float w1 = __ldg(conv_w + k1 * period + pad);
        float w2 = __ldg(conv_w + k2 * period + pad);
        areg[kt][0] = f2tf32(__ldg(lin_w + d1 * KDIM + k1) * w1);
        areg[kt][1] = f2tf32(__ldg(lin_w + d2 * KDIM + k1) * w1);
        areg[kt][2] = f2tf32(__ldg(lin_w + d1 * KDIM + k2) * w2);
        areg[kt][3] = f2tf32(__ldg(lin_w + d2 * KDIM + k2) * w2);
    }
    const float bia1 = __ldg(lin_b + d1), bia2 = __ldg(lin_b + d2);
    if (tid < NDIM) {
        s_gam[tid] = ln_g[tid];
        s_bet[tid] = ln_bt[tid];
    }

    // ---- kh1-only: cp.async stage of raw x (64 rows x 64 f4 chunks) ----
    auto stage_tile = [&](int tile, int it_idx) {
        if (tile >= ntiles) return;
        const int dslot = it_idx & 1;
        const int nslot = it_idx & (NSLOTS - 1);
        uint32_t* dstS = sX + (size_t)dslot * TILE_M * SX_STRIDE;
        const int t = tid - 256;          // 0..255
#pragma unroll
        for (int i = 0; i < 16; i++) {
            int idx = i * 256 + t;        // 4096 chunks of 16B
            int row = idx >> 6, c = idx & 63;
            long long gr = (long long)tile * TILE_M + row;
            const float4* src;
            if (c < 32) {
                src = (const float4*)messages + gr * 32 + c;
            } else {
                int nd = __ldg(node_ids + gr);
                if (c == 32) s_node[nslot * TILE_M + row] = nd;
                src = (const float4*)node_mem + (long long)nd * 32 + (c - 32);
            }
            cp_async16(smem_u32(dstS + row * SX_STRIDE + c * 4), src);
        }
    };

    // ---- kh1-only: convert+permute a staged slot to paired tf32 ----
    auto convert_slot = [&](int it_idx) {
        uint32_t* slotS = sX + (size_t)(it_idx & 1) * TILE_M * SX_STRIDE;
        const int t = tid - 256;          // 0..255
#pragma unroll
        for (int i = 0; i < 8; i++) {
            int g = i * 256 + t;          // 2048 groups
            int row = g >> 5, kg = g & 31;
            uint32_t* p = slotS + row * SX_STRIDE + kg * 8;
            float4 f0 = *(float4*)p;
            float4 f1 = *(float4*)(p + 4);
            uint4 u0 = make_uint4(f2tf32(f0.x), f2tf32(f1.x),
                                  f2tf32(f0.y), f2tf32(f1.y));
            uint4 u1 = make_uint4(f2tf32(f0.z), f2tf32(f1.z),
                                  f2tf32(f0.w), f2tf32(f1.w));
            *(uint4*)p = u0;
            *(uint4*)(p + 4) = u1;
        }
    };

    // ---- prologue: kh1 stages tiles 0,1 and converts tile 0 ----
    if (kh == 1) {
        stage_tile(blockIdx.x, 0);
        CP_COMMIT();
        stage_tile(blockIdx.x + gridDim.x, 1);
        CP_COMMIT();
        CP_WAIT1();                       // this thread's tile-0 chunks landed
        KH1_BAR();                        // ALL kh1 threads' chunks visible
        if (blockIdx.x < ntiles) convert_slot(0);
    }

    for (int it = 0;; it++) {
        int tile = blockIdx.x + it * gridDim.x;
        if (tile >= ntiles) break;
        const int dslot = it & 1;
        const int nslot = it & (NSLOTS - 1);

        __syncthreads();          // converted slot + s_node visible

        // ======== MMA: per warp 16 d x 64 batch, K-half ========
        const uint32_t* xb = sX + (size_t)dslot * TILE_M * SX_STRIDE
                           + (lane >> 2) * SX_STRIDE + kh * 128 + kbase * 2;
        float cacc[8][4];
#pragma unroll
        for (int nt = 0; nt < 8; nt++)
#pragma unroll
            for (int j = 0; j < 4; j++) cacc[nt][j] = 0.f;

#pragma unroll
        for (int kt = 0; kt < 16; kt++) {
            uint2 bp[8];
#pragma unroll
            for (int nt = 0; nt < 8; nt++)
                bp[nt] = *(const uint2*)(xb + nt * 8 * SX_STRIDE + kt * 8);
#pragma unroll
            for (int nt = 0; nt < 8; nt++)
                mma_tf32(cacc[nt], areg[kt][0], areg[kt][1],
                         areg[kt][2], areg[kt][3], bp[nt].x, bp[nt].y);
        }

        // ---- K-high warps publish partials ----
        if (kh == 1) {
#pragma unroll
            for (int nt = 0; nt < 8; nt++)
                s_comb[(dblk * 8 + nt) * 32 + lane] =
                    make_float4(cacc[nt][0], cacc[nt][1], cacc[nt][2], cacc[nt][3]);
        }
        __syncthreads();          // sX slot free + s_comb visible

        if (kh == 1) {
            // ===== kh1: stage tile it+2, wait for it+1, convert it+1 =====
            stage_tile(tile + 2 * gridDim.x, it + 2);
            CP_COMMIT();
            CP_WAIT1();           // this thread's tile-(it+1) chunks landed
            KH1_BAR();            // ALL kh1 threads' chunks visible
            if (tile + gridDim.x < ntiles) convert_slot(it + 1);
        } else {
            // ============ kh0: combine + bias -> sD =======================
#pragma unroll
            for (int nt = 0; nt < 8; nt++) {
                float4 p = s_comb[(dblk * 8 + nt) * 32 + lane];
                int brA = nt * 8 + (lane & 3) * 2;
                sD[brA * SD_STRIDE + d1]       = cacc[nt][0] + p.x + bia1;
                sD[(brA + 1) * SD_STRIDE + d1] = cacc[nt][1] + p.y + bia1;
                sD[brA * SD_STRIDE + d2]       = cacc[nt][2] + p.z + bia2;
                sD[(brA + 1) * SD_STRIDE + d2] = cacc[nt][3] + p.w + bia2;
            }
            KH0_BAR();            // sD complete (kh0-only barrier)

            // ============ kh0: LayerNorm + coalesced scatter (2 passes) ====
#pragma unroll
            for (int p = 0; p < 2; p++) {
                const int r  = p * 32 + (tid >> 3);   // row 0..63
                const int cc = tid & 7;
                float4 v[4];
                float vsum = 0.f, vsq = 0.f;
#pragma unroll
                for (int j = 0; j < 4; j++) {
                    v[j] = *(const float4*)&sD[r * SD_STRIDE + (cc + 8 * j) * 4];
                    vsum += v[j].x + v[j].y + v[j].z + v[j].w;
                    vsq  += v[j].x * v[j].x + v[j].y * v[j].y
                          + v[j].z * v[j].z + v[j].w * v[j].w;
                }
                vsum += __shfl_xor_sync(0xffffffffu, vsum, 1);
                vsq  += __shfl_xor_sync(0xffffffffu, vsq, 1);
                vsum += __shfl_xor_sync(0xffffffffu, vsum, 2);
                vsq  += __shfl_xor_sync(0xffffffffu, vsq, 2);
                vsum += __shfl_xor_sync(0xffffffffu, vsum, 4);
                vsq  += __shfl_xor_sync(0xffffffffu, vsq, 4);
                float mean = vsum * (1.0f / 128.0f);
                float var  = vsq * (1.0f / 128.0f) - mean * mean;
                float rstd = rsqrtf(var + 1e-5f);

                long long nd = s_node[nslot * TILE_M + r];
                float* orow = out + nd * NDIM;
#pragma unroll
                for (int j = 0; j < 4; j++) {
                    int cb = (cc + 8 * j) * 4;
                    const float4 g  = *(const float4*)&s_gam[cb];
                    const float4 bt = *(const float4*)&s_bet[cb];
                    float4 o;
                    o.x = (v[j].x - mean) * rstd * g.x + bt.x;
                    o.y = (v[j].y - mean) * rstd * g.y + bt.y;
                    o.z = (v[j].z - mean) * rstd * g.z + bt.z;
                    o.w = (v[j].w - mean) * rstd * g.w + bt.w;
                    *(float4*)&orow[cb] = o;
                }
            }
        }
        // loop-top __syncthreads rejoins kh0/kh1
    }
}

// ============================================================================
// launch — copy runs on a side stream CONCURRENTLY with the gemm
// ============================================================================
extern "C" void kernel_launch(void* const* d_in, const int* in_sizes, int n_in,
                              void* d_out, int out_size) {
    const int*   node_ids = (const int*)  d_in[0];
    const float* messages = (const float*)d_in[1];
    const float* node_mem = (const float*)d_in[2];
    const float* conv_w   = (const float*)d_in[3];
    const float* lin_w    = (const float*)d_in[4];
    const float* lin_b    = (const float*)d_in[5];
    const float* ln_g     = (const float*)d_in[6];
    const float* ln_bt    = (const float*)d_in[7];
    float* out = (float*)d_out;

    int Btot    = in_sizes[1] / NDIM;            // 262144
    int ntiles  = Btot / TILE_M;                 // 4096
    int period  = in_sizes[3] / KDIM;            // 7
    int pad     = period / 2;                    // 3 (L == 1 path)
    int nf4     = out_size / 4;

    const int dyn_smem = 2 * TILE_M * SX_STRIDE * 4       // x ping-pong
                       + 2048 * 16                        // s_comb
                       + TILE_M * SD_STRIDE * 4           // sD
                       + NSLOTS * TILE_M * 4 + 2 * NDIM * 4;

    // one-time setup on the first (uncaptured, correctness) call: smem attr,
    // side stream + fork/join events (none of this allocates device memory)
    static cudaStream_t side = nullptr;
    static cudaEvent_t  ev_fork = nullptr, ev_join = nullptr;
    static int configured = 0;
    if (!configured) {
        cudaFuncSetAttribute(rhythm_gemm, cudaFuncAttributeMaxDynamicSharedMemorySize,
                             dyn_smem);
        cudaStreamCreateWithFlags(&side, cudaStreamNonBlocking);
        cudaEventCreateWithFlags(&ev_fork, cudaEventDisableTiming);
        cudaEventCreateWithFlags(&ev_join, cudaEventDisableTiming);
        configured = 1;
    }

    // mask of rows updated by the scatter (default stream)
    k_clear<<<64, 256>>>((1 << 20) / 16);
    k_mark<<<(Btot + 255) / 256, 256>>>(node_ids, Btot);

    // fork: side stream starts after the mask is complete
    cudaEventRecord(ev_fork, 0);
    cudaStreamWaitEvent(side, ev_fork, 0);

    // masked copy on the SIDE stream (concurrent with gemm)
    k_copy_masked<<<2048, 256, 0, side>>>((const float4*)node_mem, (float4*)out, nf4);
    cudaEventRecord(ev_join, side);

    // gemm on the default stream (also ordered after the mask)
    rhythm_gemm<<<NCTAS, NTHREADS, dyn_smem>>>(node_ids, messages, node_mem, conv_w,
                                               lin_w, lin_b, ln_g, ln_bt, out,
                                               ntiles, period, pad);

    // join: downstream work (harness) sees both branches complete
    cudaStreamWaitEvent(0, ev_join, 0);
}